// round 15
// baseline (speedup 1.0000x reference)
#include <cuda_runtime.h>
#include <cstdint>

#define NPIX   9216
#define HW_    96
#define CIN_   256
#define EMB1_  256
#define EMB2_  128
#define NCLS_  80
#define NEG_   3
#define BATCH_ 8

// ---------------- device scratch (allocation-free) ----------------
__device__ float g_xf [(size_t)BATCH_ * NPIX * CIN_];   // x NHWC, tf32-rounded fp32
__device__ float g_hf [(size_t)BATCH_ * NPIX * EMB1_];  // conv1+BN out, tf32-rounded fp32
__device__ float g_emb[(size_t)BATCH_ * NPIX * EMB2_];  // conv2 out, NORMALIZED, pixel-major
__device__ float g_wf1[EMB1_ * 9 * 256];                // W1 as [co][tap][ci], tf32-rounded
__device__ float g_wf2[EMB2_ * 9 * 256];                // W2 same
__device__ float g_reps[NCLS_ * EMB2_];
__device__ float g_repsneg[NCLS_ * NEG_ * EMB2_];

// ---------------- helpers ----------------
__device__ __forceinline__ float to_tf32(float x) {
    uint32_t u;
    asm("cvt.rna.tf32.f32 %0, %1;" : "=r"(u) : "f"(x));
    return __uint_as_float(u);
}
__device__ __forceinline__ uint32_t smem_u32(const void* p) {
    uint32_t a;
    asm("{ .reg .u64 t; cvta.to.shared.u64 t, %1; cvt.u32.u64 %0, t; }" : "=r"(a) : "l"(p));
    return a;
}
#define MMA_TF32(d, a, b0, b1) \
    asm volatile("mma.sync.aligned.m16n8k8.row.col.f32.tf32.tf32.f32 " \
        "{%0,%1,%2,%3}, {%4,%5,%6,%7}, {%8,%9}, {%0,%1,%2,%3};" \
        : "+f"((d)[0]), "+f"((d)[1]), "+f"((d)[2]), "+f"((d)[3]) \
        : "r"((a)[0]), "r"((a)[1]), "r"((a)[2]), "r"((a)[3]), "r"(b0), "r"(b1))
#define CP_ASYNC16(dst, src, sz) \
    asm volatile("cp.async.cg.shared.global [%0], [%1], 16, %2;" \
        :: "r"(dst), "l"(src), "r"(sz) : "memory")
#define CP_COMMIT() asm volatile("cp.async.commit_group;" ::: "memory")
#define CP_WAIT0()  asm volatile("cp.async.wait_group 0;" ::: "memory")

// ---------------------------------------------------------------------------
// pre-pass: x NCHW fp32 -> NHWC tf32-rounded fp32
// ---------------------------------------------------------------------------
__global__ __launch_bounds__(256)
void transpose_x_kernel(const float* __restrict__ x)
{
    __shared__ float s32[256 * 33];
    const int tid = threadIdx.x;
    const int b = blockIdx.y;
    const int p0 = blockIdx.x * 32;
    const int pxr = tid & 31, chb = tid >> 5;
#pragma unroll 4
    for (int pass = 0; pass < 32; ++pass) {
        int ch = pass * 8 + chb;
        s32[ch * 33 + pxr] = to_tf32(x[((size_t)(b * 256 + ch)) * NPIX + p0 + pxr]);
    }
    __syncthreads();
    for (int px = 0; px < 32; ++px) {
        g_xf[((size_t)(b * NPIX + p0 + px)) * 256 + tid] = s32[tid * 33 + px];
    }
}

// ---------------------------------------------------------------------------
// pre-pass: W [co][256][3][3] fp32 -> [co][tap][ci] tf32-rounded fp32
// ---------------------------------------------------------------------------
__global__ __launch_bounds__(256)
void wprep_kernel(const float* __restrict__ w, float* __restrict__ dst, int total)
{
    int i = blockIdx.x * 256 + threadIdx.x;
    if (i >= total) return;
    int co = i / 2304, r = i - co * 2304;
    int t = r >> 8;
    int ci = r & 255;
    dst[i] = to_tf32(w[((size_t)(co * 256 + ci)) * 9 + t]);
}

// ---------------------------------------------------------------------------
// staging via cp.async (16B, zero-fill OOB); smem row stride 36 floats
// ---------------------------------------------------------------------------
__device__ __forceinline__ void stage_X_async(uint32_t xdst, const float* __restrict__ src,
                                              int b, int y0, int c, int tid)
{
    for (int i = tid; i < 3136; i += 256) {     // 4 rows x 98 xpos x 8 groups
        int pos = i >> 3, g = i & 7;
        int yrow = pos / 98, xpos = pos - yrow * 98;
        int y = y0 + yrow - 1, xc = xpos - 1;
        int ok = ((unsigned)y < 96u) && ((unsigned)xc < 96u);
        const float* gs = ok ? (src + ((size_t)(b * NPIX + y * 96 + xc)) * 256 + c * 32 + g * 4)
                             : src;
        CP_ASYNC16(xdst + (uint32_t)(pos * 144 + g * 16), gs, ok ? 16 : 0);
    }
}
__device__ __forceinline__ void stage_W_async(uint32_t wdst, const float* __restrict__ wsrc,
                                              int co0, int c, int tap, int tid)
{
    for (int i = tid; i < 1024; i += 256) {     // 128 co x 8 groups
        int co = i >> 3, g = i & 7;
        const float* gs = wsrc + ((size_t)((co0 + co) * 9 + tap)) * 256 + c * 32 + g * 4;
        CP_ASYNC16(wdst + (uint32_t)(co * 144 + g * 16), gs, 16);
    }
}

// ---------------------------------------------------------------------------
// tf32 mma conv: 2 CTAs/SM, cp.async pipeline, scalar LDS.32 fragments.
// NEW warp tiling (mt=4, nt=6): warp = 64 co x 48 px -> crossbar bytes -12.5%.
// 8 warps = 2 co-groups x 4 px-groups. CTA = 128 co x 192 px (2 image rows).
// STAGE 1: g_xf -> g_hf (BN folded).
// STAGE 2: g_hf -> g_emb (bias + FUSED L2 normalize).
// ---------------------------------------------------------------------------
template<int STAGE>
__global__ __launch_bounds__(256, 2)
void conv_tf32(const float* __restrict__ bias,
               const float* __restrict__ gamma,
               const float* __restrict__ beta,
               const float* __restrict__ mean,
               const float* __restrict__ var)
{
    extern __shared__ float smf[];
    float* Xall = smf;               // [14112]  (4 rows x 98 x stride36)
    float* Wall = smf + 14112;       // [2][4608] (128 co x stride36)

    const int tid = threadIdx.x, wid = tid >> 5, lane = tid & 31;
    const int y0 = blockIdx.x * 2;
    const int b  = blockIdx.y;
    const int co0 = blockIdx.z * 128;
    const int wc = wid & 1;          // co-group (64 co)
    const int wp = wid >> 1;         // px-group (48 px)
    const int gid = lane >> 2, tig = lane & 3;

    const float* __restrict__ src  = (STAGE == 1) ? g_xf : g_hf;
    const float* __restrict__ wsrc = (STAGE == 1) ? g_wf1 : g_wf2;

    const uint32_t smb = smem_u32(smf);
    const uint32_t xbase = smb;
    const uint32_t wbase[2] = { smb + 14112u * 4u, smb + (14112u + 4608u) * 4u };

    float acc[4][6][4];
#pragma unroll
    for (int m = 0; m < 4; ++m)
#pragma unroll
        for (int n = 0; n < 6; ++n)
#pragma unroll
            for (int q = 0; q < 4; ++q) acc[m][n][q] = 0.f;

    int aidx[4], xidx[6];
#pragma unroll
    for (int mi = 0; mi < 4; ++mi)
        aidx[mi] = (wc * 64 + mi * 16 + gid) * 36 + tig;
#pragma unroll
    for (int p = 0; p < 6; ++p)
        xidx[p] = ((wp >> 1) * 98 + (wp & 1) * 48 + p * 8 + gid) * 36 + tig;

    // prologue
    stage_X_async(xbase, src, b, y0, 0, tid);
    stage_W_async(wbase[0], wsrc, co0, 0, 0, tid);
    CP_COMMIT();

    int it = 0;
    for (int c = 0; c < 8; ++c) {
        for (int tap = 0; tap < 9; ++tap, ++it) {
            CP_WAIT0();
            __syncthreads();
            if (it < 71) {
                const int itn = it + 1, cn = itn / 9, tapn = itn - cn * 9;
                stage_W_async(wbase[itn & 1], wsrc, co0, cn, tapn, tid);
                CP_COMMIT();
            }
            const uint32_t* Wsu = reinterpret_cast<const uint32_t*>(Wall + (it & 1) * 4608);
            const uint32_t* Xhu = reinterpret_cast<const uint32_t*>(Xall);
            const int kr = tap / 3, kc = tap - kr * 3;
            const int toff = (kr * 98 + kc) * 36;
#pragma unroll
            for (int ks = 0; ks < 4; ++ks) {
                const int k0 = ks * 8;
                // B fragments first (loaded once, used by all 4 mi)
                uint32_t bf[6][2];
#pragma unroll
                for (int p = 0; p < 6; ++p) {
                    bf[p][0] = Xhu[xidx[p] + toff + k0];
                    bf[p][1] = Xhu[xidx[p] + toff + k0 + 4];
                }
#pragma unroll
                for (int mi = 0; mi < 4; ++mi) {
                    uint32_t a[4];
                    a[0] = Wsu[aidx[mi] + k0];
                    a[1] = Wsu[aidx[mi] + k0 + 8 * 36];
                    a[2] = Wsu[aidx[mi] + k0 + 4];
                    a[3] = Wsu[aidx[mi] + k0 + 8 * 36 + 4];
#pragma unroll
                    for (int p = 0; p < 6; ++p)
                        MMA_TF32(acc[mi][p], a, bf[p][0], bf[p][1]);
                }
            }
        }
        if (c < 7) {
            __syncthreads();                       // all X reads of this chunk done
            stage_X_async(xbase, src, b, y0, c + 1, tid);
            CP_COMMIT();
        }
    }

    if (STAGE == 1) {
        const size_t pixb = (size_t)b * NPIX + (size_t)(y0 + (wp >> 1)) * 96;
        const int pxb = (wp & 1) * 48;
#pragma unroll
        for (int mi = 0; mi < 4; ++mi) {
            const int clo = co0 + wc * 64 + mi * 16 + gid;
            const int chi = clo + 8;
            float blo = bias[clo], bhi = bias[chi];
            float slo = gamma[clo] * rsqrtf(var[clo] + 1e-5f);
            float shi = gamma[chi] * rsqrtf(var[chi] + 1e-5f);
            float mlo = mean[clo], mhi = mean[chi];
            float elo = beta[clo], ehi = beta[chi];
#pragma unroll
            for (int n = 0; n < 6; ++n) {
                const int px0 = pxb + n * 8 + tig * 2;
#pragma unroll
                for (int j = 0; j < 2; ++j) {
                    float vlo = (acc[mi][n][j]     + blo - mlo) * slo + elo;
                    float vhi = (acc[mi][n][j + 2] + bhi - mhi) * shi + ehi;
                    const size_t pix = pixb + px0 + j;
                    g_hf[pix * 256 + clo] = to_tf32(vlo);
                    g_hf[pix * 256 + chi] = to_tf32(vhi);
                }
            }
        }
    } else {
        // fused bias + L2 normalize via smem overlay Es[192][132] (25344 floats)
        __syncthreads();               // all fragment LDS of last tap complete
        float* Es = smf;
#pragma unroll
        for (int mi = 0; mi < 4; ++mi) {
            const int clo = wc * 64 + mi * 16 + gid;     // co0 == 0 for conv2
            const int chi = clo + 8;
            float blo = bias[clo], bhi = bias[chi];
#pragma unroll
            for (int n = 0; n < 6; ++n) {
                const int lp = wp * 48 + n * 8 + tig * 2;
#pragma unroll
                for (int j = 0; j < 2; ++j) {
                    Es[(lp + j) * 132 + clo] = acc[mi][n][j]     + blo;
                    Es[(lp + j) * 132 + chi] = acc[mi][n][j + 2] + bhi;
                }
            }
        }
        __syncthreads();
        const size_t pixb = (size_t)b * NPIX + (size_t)y0 * 96;
        for (int p = wid * 24; p < wid * 24 + 24; ++p) {
            float4 v = *reinterpret_cast<const float4*>(&Es[p * 132 + lane * 4]);
            float ss = v.x * v.x + v.y * v.y + v.z * v.z + v.w * v.w;
#pragma unroll
            for (int o = 16; o > 0; o >>= 1) ss += __shfl_xor_sync(0xffffffffu, ss, o);
            float sc = 1.f / fmaxf(sqrtf(ss), 1e-12f);
            v.x *= sc; v.y *= sc; v.z *= sc; v.w *= sc;
            *reinterpret_cast<float4*>(&g_emb[(pixb + p) * 128 + lane * 4]) = v;
        }
    }
}

// ---------------------------------------------------------------------------
// reps prep v6: grid (class, neg) -> serial depth 3 layers.
// ---------------------------------------------------------------------------
__device__ __forceinline__ float block_sumsq_128(float v, float* red4)
{
    float s = v * v;
#pragma unroll
    for (int o = 16; o > 0; o >>= 1) s += __shfl_xor_sync(0xffffffffu, s, o);
    const int wid = threadIdx.x >> 5, lane = threadIdx.x & 31;
    if (lane == 0) red4[wid] = s;
    __syncthreads();
    float tot = red4[0] + red4[1] + red4[2] + red4[3];
    __syncthreads();
    return tot;
}

__global__ __launch_bounds__(128)
void prep_reps_v6(const float* __restrict__ rep_w,
                  const float* __restrict__ rep_b,
                  const float* __restrict__ neg_w,
                  const float* __restrict__ neg_b)
{
    __shared__ float h_a[128];
    __shared__ float h_b[128];
    __shared__ float red4[4];

    const int j = threadIdx.x, c = blockIdx.x, n = blockIdx.y;
    const int w = j >> 5, lane = j & 31;

    float v = rep_w[c * 128 + j] + rep_b[c * 128 + j];
    float tot = block_sumsq_128(v, red4);
    float scale = 1.f / fmaxf(sqrtf(tot), 1e-12f);
    h_a[j] = v * scale;
    if (n == 0) g_reps[c * 128 + j] = v * scale;
    __syncthreads();

    float* cur = h_a;
    float* nxt = h_b;
#pragma unroll
    for (int i = 0; i < 3; ++i) {
        const float* W = neg_w + (size_t)((n * 3 + i) * 128) * 128;
        const float* bb = neg_b + (n * 3 + i) * 128;
        float4 sv = *reinterpret_cast<const float4*>(&cur[lane * 4]);
#pragma unroll 4
        for (int t = 0; t < 32; ++t) {
            int jo = w * 32 + t;
            float4 wv = *reinterpret_cast<const float4*>(&W[(size_t)jo * 128 + lane * 4]);
            float d = wv.x * sv.x + wv.y * sv.y + wv.z * sv.z + wv.w * sv.w;
#pragma unroll
            for (int o = 16; o > 0; o >>= 1) d += __shfl_xor_sync(0xffffffffu, d, o);
            if (lane == 0) {
                d += bb[jo];
                if (i < 2) d = fmaxf(d, 0.f);
                nxt[jo] = d;
            }
        }
        __syncthreads();
        float* tmp = cur; cur = nxt; nxt = tmp;
    }
    float f = cur[j];
    float t2 = block_sumsq_128(f, red4);
    float sc2 = 1.f / fmaxf(sqrtf(t2), 1e-12f);
    g_repsneg[((size_t)c * NEG_ + n) * 128 + j] = f * sc2;
}

// ---------------------------------------------------------------------------
// dot + epilogue (proven FFMA): 64-px x 16-class tile.
// ---------------------------------------------------------------------------
__global__ __launch_bounds__(256)
void dot_out_v4(float* __restrict__ out)
{
    extern __shared__ float smd[];
    float* e_s  = smd;                 // [128 ch][stride 68]
    float* rp_s = smd + 8704;          // [16 cls][128]
    float* rn_s = smd + 8704 + 2048;   // [16 cls][3][128]

    const int tid = threadIdx.x;
    const int b  = blockIdx.y;
    const int p0 = blockIdx.x * 64;
    const int c0 = blockIdx.z * 16;

    for (int i = tid; i < 8192; i += 256) {
        int px = i >> 7, ch = i & 127;
        e_s[ch * 68 + px] = g_emb[((size_t)(b * NPIX + p0 + px)) * 128 + ch];
    }
    for (int i = tid; i < 2048; i += 256) rp_s[i] = g_reps[c0 * EMB2_ + i];
    for (int i = tid; i < 6144; i += 256) rn_s[i] = g_repsneg[c0 * NEG_ * EMB2_ + i];
    __syncthreads();

    const int cc = tid >> 4;
    const int pg = tid & 15;
    const float* rpp = rp_s + cc * 128;
    const float* rn0 = rn_s + (cc * 3 + 0) * 128;
    const float* rn1 = rn_s + (cc * 3 + 1) * 128;
    const float* rn2 = rn_s + (cc * 3 + 2) * 128;

    float ap[4] = {0, 0, 0, 0};
    float a0[4] = {0, 0, 0, 0};
    float a1[4] = {0, 0, 0, 0};
    float a2[4] = {0, 0, 0, 0};

#pragma unroll 4
    for (int ch = 0; ch < 128; ++ch) {
        float4 ev = *reinterpret_cast<const float4*>(&e_s[ch * 68 + pg * 4]);
        float wp = rpp[ch], w0 = rn0[ch], w1 = rn1[ch], w2 = rn2[ch];
        ap[0] = fmaf(ev.x, wp, ap[0]); ap[1] = fmaf(ev.y, wp, ap[1]);
        ap[2] = fmaf(ev.z, wp, ap[2]); ap[3] = fmaf(ev.w, wp, ap[3]);
        a0[0] = fmaf(ev.x, w0, a0[0]); a0[1] = fmaf(ev.y, w0, a0[1]);
        a0[2] = fmaf(ev.z, w0, a0[2]); a0[3] = fmaf(ev.w, w0, a0[3]);
        a1[0] = fmaf(ev.x, w1, a1[0]); a1[1] = fmaf(ev.y, w1, a1[1]);
        a1[2] = fmaf(ev.z, w1, a1[2]); a1[3] = fmaf(ev.w, w1, a1[3]);
        a2[0] = fmaf(ev.x, w2, a2[0]); a2[1] = fmaf(ev.y, w2, a2[1]);
        a2[2] = fmaf(ev.z, w2, a2[2]); a2[3] = fmaf(ev.w, w2, a2[3]);
    }

    const int c = c0 + cc;
    const size_t S = (size_t)BATCH_ * NCLS_ * NPIX;
    float* out_cls  = out;
    float* out_csn  = out + S;
    float* out_dist = out + 2 * S;
    float* out_dneg = out + 3 * S;
    float* out_pori = out + 6 * S;

    const size_t base   = ((size_t)b * NCLS_ + c) * NPIX + p0 + pg * 4;
    const size_t dnbase = ((size_t)(b * NCLS_ + c) * 3) * NPIX + p0 + pg * 4;

#pragma unroll
    for (int jx = 0; jx < 4; ++jx) {
        float dist = sqrtf(fmaxf(2.f - 2.f * ap[jx], 0.f));
        float dn0  = sqrtf(fmaxf(2.f - 2.f * a0[jx], 0.f));
        float dn1  = sqrtf(fmaxf(2.f - 2.f * a1[jx], 0.f));
        float dn2  = sqrtf(fmaxf(2.f - 2.f * a2[jx], 0.f));

        float pn0 = expf(-dn0 * dn0 * 2.f);
        float pn1 = expf(-dn1 * dn1 * 2.f);
        float pn2 = expf(-dn2 * dn2 * 2.f);
        float csn = fmaxf(pn0, fmaxf(pn1, pn2));

        float minn = fminf(dn0, fminf(dn1, dn2));
        float shifted = dist + 0.3f * fmaxf(2.f - minn, 0.f);
        float pr = expf(-shifted * shifted * 2.f);
        float cs = fminf(fmaxf(pr, 0.f), 1.f);
        float cls = logf(fmaxf(cs, 1e-5f) / fmaxf(1.f - cs, 1e-5f));
        float pori = expf(-dist * dist * 2.f);

        out_cls [base + jx] = cls;
        out_csn [base + jx] = csn;
        out_dist[base + jx] = dist;
        out_pori[base + jx] = pori;
        out_dneg[dnbase + jx]            = dn0;
        out_dneg[dnbase + NPIX + jx]     = dn1;
        out_dneg[dnbase + 2 * NPIX + jx] = dn2;
    }
}

// ---------------------------------------------------------------------------
extern "C" void kernel_launch(void* const* d_in, const int* in_sizes, int n_in,
                              void* d_out, int out_size)
{
    const float* x      = (const float*)d_in[0];
    const float* w1     = (const float*)d_in[1];
    const float* b1     = (const float*)d_in[2];
    const float* gamma  = (const float*)d_in[3];
    const float* beta   = (const float*)d_in[4];
    const float* mean   = (const float*)d_in[5];
    const float* var    = (const float*)d_in[6];
    const float* w2     = (const float*)d_in[7];
    const float* b2     = (const float*)d_in[8];
    const float* rep_w  = (const float*)d_in[9];
    const float* rep_b  = (const float*)d_in[10];
    const float* neg_w  = (const float*)d_in[11];
    const float* neg_b  = (const float*)d_in[12];
    float* out = (float*)d_out;

    (void)in_sizes; (void)n_in; (void)out_size;

    const int CONV1_SMEM = (14112 + 9216) * 4;      // 93312 B  -> 2 CTAs/SM
    const int CONV2_SMEM = 192 * 132 * 4;           // 101376 B -> 2 CTAs/SM (Es overlay)
    cudaFuncSetAttribute(conv_tf32<1>, cudaFuncAttributeMaxDynamicSharedMemorySize, CONV1_SMEM);
    cudaFuncSetAttribute(conv_tf32<2>, cudaFuncAttributeMaxDynamicSharedMemorySize, CONV2_SMEM);
    cudaFuncSetAttribute(dot_out_v4,   cudaFuncAttributeMaxDynamicSharedMemorySize, 67584);

    float *wf1p, *wf2p;
    cudaGetSymbolAddress((void**)&wf1p, g_wf1);
    cudaGetSymbolAddress((void**)&wf2p, g_wf2);

    // pre-passes
    transpose_x_kernel<<<dim3(NPIX / 32, BATCH_), 256>>>(x);
    wprep_kernel<<<(EMB1_ * 2304 + 255) / 256, 256>>>(w1, wf1p, EMB1_ * 2304);
    wprep_kernel<<<(EMB2_ * 2304 + 255) / 256, 256>>>(w2, wf2p, EMB2_ * 2304);

    // conv1 + BN (tf32 mma, mt=4/nt=6 tiling)  [profiled slot]
    conv_tf32<1><<<dim3(48, BATCH_, 2), 256, CONV1_SMEM>>>(b1, gamma, beta, mean, var);

    // reps (independent)
    prep_reps_v6<<<dim3(NCLS_, NEG_), 128>>>(rep_w, rep_b, neg_w, neg_b);

    // conv2 + fused bias + L2 normalize
    conv_tf32<2><<<dim3(48, BATCH_, 1), 256, CONV2_SMEM>>>(b2, nullptr, nullptr, nullptr, nullptr);

    // fused dot + outputs
    dot_out_v4<<<dim3(NPIX / 64, BATCH_, NCLS_ / 16), 256, 67584>>>(out);
}

// round 16
// speedup vs baseline: 1.0359x; 1.0359x over previous
#include <cuda_runtime.h>
#include <cstdint>

#define NPIX   9216
#define HW_    96
#define CIN_   256
#define EMB1_  256
#define EMB2_  128
#define NCLS_  80
#define NEG_   3
#define BATCH_ 8

// ---------------- device scratch (allocation-free) ----------------
__device__ float g_xf [(size_t)BATCH_ * NPIX * CIN_];   // x NHWC, tf32-rounded fp32
__device__ float g_hf [(size_t)BATCH_ * NPIX * EMB1_];  // conv1+BN out, tf32-rounded fp32
__device__ float g_emb[(size_t)BATCH_ * NPIX * EMB2_];  // conv2 out, NORMALIZED, pixel-major
__device__ float g_wf1[EMB1_ * 9 * 256];                // W1 as [co][tap][ci], tf32-rounded
__device__ float g_wf2[EMB2_ * 9 * 256];                // W2 same
__device__ float g_reps[NCLS_ * EMB2_];
__device__ float g_repsneg[NCLS_ * NEG_ * EMB2_];

// ---------------- helpers ----------------
__device__ __forceinline__ float to_tf32(float x) {
    uint32_t u;
    asm("cvt.rna.tf32.f32 %0, %1;" : "=r"(u) : "f"(x));
    return __uint_as_float(u);
}
__device__ __forceinline__ uint32_t smem_u32(const void* p) {
    uint32_t a;
    asm("{ .reg .u64 t; cvta.to.shared.u64 t, %1; cvt.u32.u64 %0, t; }" : "=r"(a) : "l"(p));
    return a;
}
#define MMA_TF32(d, a, b0, b1) \
    asm volatile("mma.sync.aligned.m16n8k8.row.col.f32.tf32.tf32.f32 " \
        "{%0,%1,%2,%3}, {%4,%5,%6,%7}, {%8,%9}, {%0,%1,%2,%3};" \
        : "+f"((d)[0]), "+f"((d)[1]), "+f"((d)[2]), "+f"((d)[3]) \
        : "r"((a)[0]), "r"((a)[1]), "r"((a)[2]), "r"((a)[3]), "r"(b0), "r"(b1))
#define CP_ASYNC16(dst, src, sz) \
    asm volatile("cp.async.cg.shared.global [%0], [%1], 16, %2;" \
        :: "r"(dst), "l"(src), "r"(sz) : "memory")
#define CP_COMMIT() asm volatile("cp.async.commit_group;" ::: "memory")
#define CP_WAIT0()  asm volatile("cp.async.wait_group 0;" ::: "memory")

// ---------------------------------------------------------------------------
// pre-pass: x NCHW fp32 -> NHWC tf32-rounded fp32
// ---------------------------------------------------------------------------
__global__ __launch_bounds__(256)
void transpose_x_kernel(const float* __restrict__ x)
{
    __shared__ float s32[256 * 33];
    const int tid = threadIdx.x;
    const int b = blockIdx.y;
    const int p0 = blockIdx.x * 32;
    const int pxr = tid & 31, chb = tid >> 5;
#pragma unroll 4
    for (int pass = 0; pass < 32; ++pass) {
        int ch = pass * 8 + chb;
        s32[ch * 33 + pxr] = to_tf32(x[((size_t)(b * 256 + ch)) * NPIX + p0 + pxr]);
    }
    __syncthreads();
    for (int px = 0; px < 32; ++px) {
        g_xf[((size_t)(b * NPIX + p0 + px)) * 256 + tid] = s32[tid * 33 + px];
    }
}

// ---------------------------------------------------------------------------
// pre-pass: W [co][256][3][3] fp32 -> [co][tap][ci] tf32-rounded fp32
// ---------------------------------------------------------------------------
__global__ __launch_bounds__(256)
void wprep_kernel(const float* __restrict__ w, float* __restrict__ dst, int total)
{
    int i = blockIdx.x * 256 + threadIdx.x;
    if (i >= total) return;
    int co = i / 2304, r = i - co * 2304;
    int t = r >> 8;
    int ci = r & 255;
    dst[i] = to_tf32(w[((size_t)(co * 256 + ci)) * 9 + t]);
}

// ---------------------------------------------------------------------------
// staging via cp.async (16B, zero-fill OOB); smem row stride 36 floats
// ---------------------------------------------------------------------------
__device__ __forceinline__ void stage_X_async(uint32_t xdst, const float* __restrict__ src,
                                              int b, int y0, int c, int tid)
{
    for (int i = tid; i < 3136; i += 256) {     // 4 rows x 98 xpos x 8 groups
        int pos = i >> 3, g = i & 7;
        int yrow = pos / 98, xpos = pos - yrow * 98;
        int y = y0 + yrow - 1, xc = xpos - 1;
        int ok = ((unsigned)y < 96u) && ((unsigned)xc < 96u);
        const float* gs = ok ? (src + ((size_t)(b * NPIX + y * 96 + xc)) * 256 + c * 32 + g * 4)
                             : src;
        CP_ASYNC16(xdst + (uint32_t)(pos * 144 + g * 16), gs, ok ? 16 : 0);
    }
}
__device__ __forceinline__ void stage_W_async(uint32_t wdst, const float* __restrict__ wsrc,
                                              int co0, int c, int tap, int tid)
{
    for (int i = tid; i < 1024; i += 256) {     // 128 co x 8 groups
        int co = i >> 3, g = i & 7;
        const float* gs = wsrc + ((size_t)((co0 + co) * 9 + tap)) * 256 + c * 32 + g * 4;
        CP_ASYNC16(wdst + (uint32_t)(co * 144 + g * 16), gs, 16);
    }
}

// ---------------------------------------------------------------------------
// tf32 mma conv (R14-proven, 481us conv1): 2 CTAs/SM, cp.async pipeline,
// scalar LDS.32 fragments, mt=2/nt=12 warp tiles.
// Block = 128 co x 192 px (2 image rows), 8 warps = 4 co-quadrants x 2 rows.
// STAGE 1: g_xf -> g_hf (BN folded).
// STAGE 2: g_hf -> g_emb (bias + FUSED L2 normalize).
// ---------------------------------------------------------------------------
template<int STAGE>
__global__ __launch_bounds__(256, 2)
void conv_tf32(const float* __restrict__ bias,
               const float* __restrict__ gamma,
               const float* __restrict__ beta,
               const float* __restrict__ mean,
               const float* __restrict__ var)
{
    extern __shared__ float smf[];
    float* Xall = smf;               // [14112]  (4 rows x 98 x stride36)
    float* Wall = smf + 14112;       // [2][4608] (128 co x stride36)

    const int tid = threadIdx.x, wid = tid >> 5, lane = tid & 31;
    const int y0 = blockIdx.x * 2;
    const int b  = blockIdx.y;
    const int co0 = blockIdx.z * 128;
    const int wq = wid & 3, wh = wid >> 2;
    const int gid = lane >> 2, tig = lane & 3;

    const float* __restrict__ src  = (STAGE == 1) ? g_xf : g_hf;
    const float* __restrict__ wsrc = (STAGE == 1) ? g_wf1 : g_wf2;

    const uint32_t smb = smem_u32(smf);
    const uint32_t xbase = smb;
    const uint32_t wbase[2] = { smb + 14112u * 4u, smb + (14112u + 4608u) * 4u };

    float acc[2][12][4];
#pragma unroll
    for (int m = 0; m < 2; ++m)
#pragma unroll
        for (int n = 0; n < 12; ++n)
#pragma unroll
            for (int q = 0; q < 4; ++q) acc[m][n][q] = 0.f;

    int aidx[2], xidx[12];
#pragma unroll
    for (int mi = 0; mi < 2; ++mi)
        aidx[mi] = (wq * 32 + mi * 16 + gid) * 36 + tig;
#pragma unroll
    for (int p = 0; p < 12; ++p)
        xidx[p] = (wh * 98 + p * 8 + gid) * 36 + tig;

    // prologue
    stage_X_async(xbase, src, b, y0, 0, tid);
    stage_W_async(wbase[0], wsrc, co0, 0, 0, tid);
    CP_COMMIT();

    int it = 0;
    for (int c = 0; c < 8; ++c) {
        for (int tap = 0; tap < 9; ++tap, ++it) {
            CP_WAIT0();
            __syncthreads();
            if (it < 71) {
                const int itn = it + 1, cn = itn / 9, tapn = itn - cn * 9;
                stage_W_async(wbase[itn & 1], wsrc, co0, cn, tapn, tid);
                CP_COMMIT();
            }
            const uint32_t* Wsu = reinterpret_cast<const uint32_t*>(Wall + (it & 1) * 4608);
            const uint32_t* Xhu = reinterpret_cast<const uint32_t*>(Xall);
            const int kr = tap / 3, kc = tap - kr * 3;
            const int toff = (kr * 98 + kc) * 36;
#pragma unroll
            for (int ks = 0; ks < 4; ++ks) {
                const int k0 = ks * 8;
                uint32_t a[2][4];
#pragma unroll
                for (int mi = 0; mi < 2; ++mi) {
                    a[mi][0] = Wsu[aidx[mi] + k0];
                    a[mi][1] = Wsu[aidx[mi] + k0 + 8 * 36];
                    a[mi][2] = Wsu[aidx[mi] + k0 + 4];
                    a[mi][3] = Wsu[aidx[mi] + k0 + 8 * 36 + 4];
                }
#pragma unroll
                for (int p = 0; p < 12; ++p) {
                    uint32_t b0 = Xhu[xidx[p] + toff + k0];
                    uint32_t b1 = Xhu[xidx[p] + toff + k0 + 4];
                    MMA_TF32(acc[0][p], a[0], b0, b1);
                    MMA_TF32(acc[1][p], a[1], b0, b1);
                }
            }
        }
        if (c < 7) {
            __syncthreads();                       // all X reads of this chunk done
            stage_X_async(xbase, src, b, y0, c + 1, tid);
            CP_COMMIT();
        }
    }

    if (STAGE == 1) {
        const size_t pixb = (size_t)b * NPIX + (size_t)(y0 + wh) * 96;
#pragma unroll
        for (int mi = 0; mi < 2; ++mi) {
            const int clo = co0 + wq * 32 + mi * 16 + gid;
            const int chi = clo + 8;
            float blo = bias[clo], bhi = bias[chi];
            float slo = gamma[clo] * rsqrtf(var[clo] + 1e-5f);
            float shi = gamma[chi] * rsqrtf(var[chi] + 1e-5f);
            float mlo = mean[clo], mhi = mean[chi];
            float elo = beta[clo], ehi = beta[chi];
#pragma unroll
            for (int n = 0; n < 12; ++n) {
                const int px0 = n * 8 + tig * 2;
#pragma unroll
                for (int j = 0; j < 2; ++j) {
                    float vlo = (acc[mi][n][j]     + blo - mlo) * slo + elo;
                    float vhi = (acc[mi][n][j + 2] + bhi - mhi) * shi + ehi;
                    const size_t pix = pixb + px0 + j;
                    g_hf[pix * 256 + clo] = to_tf32(vlo);
                    g_hf[pix * 256 + chi] = to_tf32(vhi);
                }
            }
        }
    } else {
        // fused bias + L2 normalize via smem overlay Es[192][132] (25344 floats)
        __syncthreads();               // all fragment LDS of last tap complete
        float* Es = smf;
#pragma unroll
        for (int mi = 0; mi < 2; ++mi) {
            const int clo = wq * 32 + mi * 16 + gid;     // co0 == 0 for conv2
            const int chi = clo + 8;
            float blo = bias[clo], bhi = bias[chi];
#pragma unroll
            for (int n = 0; n < 12; ++n) {
                const int lp = wh * 96 + n * 8 + tig * 2;
#pragma unroll
                for (int j = 0; j < 2; ++j) {
                    Es[(lp + j) * 132 + clo] = acc[mi][n][j]     + blo;
                    Es[(lp + j) * 132 + chi] = acc[mi][n][j + 2] + bhi;
                }
            }
        }
        __syncthreads();
        const size_t pixb = (size_t)b * NPIX + (size_t)y0 * 96;
        for (int p = wid * 24; p < wid * 24 + 24; ++p) {
            float4 v = *reinterpret_cast<const float4*>(&Es[p * 132 + lane * 4]);
            float ss = v.x * v.x + v.y * v.y + v.z * v.z + v.w * v.w;
#pragma unroll
            for (int o = 16; o > 0; o >>= 1) ss += __shfl_xor_sync(0xffffffffu, ss, o);
            float sc = 1.f / fmaxf(sqrtf(ss), 1e-12f);
            v.x *= sc; v.y *= sc; v.z *= sc; v.w *= sc;
            *reinterpret_cast<float4*>(&g_emb[(pixb + p) * 128 + lane * 4]) = v;
        }
    }
}

// ---------------------------------------------------------------------------
// reps prep v6: grid (class, neg) -> serial depth 3 layers.
// ---------------------------------------------------------------------------
__device__ __forceinline__ float block_sumsq_128(float v, float* red4)
{
    float s = v * v;
#pragma unroll
    for (int o = 16; o > 0; o >>= 1) s += __shfl_xor_sync(0xffffffffu, s, o);
    const int wid = threadIdx.x >> 5, lane = threadIdx.x & 31;
    if (lane == 0) red4[wid] = s;
    __syncthreads();
    float tot = red4[0] + red4[1] + red4[2] + red4[3];
    __syncthreads();
    return tot;
}

__global__ __launch_bounds__(128)
void prep_reps_v6(const float* __restrict__ rep_w,
                  const float* __restrict__ rep_b,
                  const float* __restrict__ neg_w,
                  const float* __restrict__ neg_b)
{
    __shared__ float h_a[128];
    __shared__ float h_b[128];
    __shared__ float red4[4];

    const int j = threadIdx.x, c = blockIdx.x, n = blockIdx.y;
    const int w = j >> 5, lane = j & 31;

    float v = rep_w[c * 128 + j] + rep_b[c * 128 + j];
    float tot = block_sumsq_128(v, red4);
    float scale = 1.f / fmaxf(sqrtf(tot), 1e-12f);
    h_a[j] = v * scale;
    if (n == 0) g_reps[c * 128 + j] = v * scale;
    __syncthreads();

    float* cur = h_a;
    float* nxt = h_b;
#pragma unroll
    for (int i = 0; i < 3; ++i) {
        const float* W = neg_w + (size_t)((n * 3 + i) * 128) * 128;
        const float* bb = neg_b + (n * 3 + i) * 128;
        float4 sv = *reinterpret_cast<const float4*>(&cur[lane * 4]);
#pragma unroll 4
        for (int t = 0; t < 32; ++t) {
            int jo = w * 32 + t;
            float4 wv = *reinterpret_cast<const float4*>(&W[(size_t)jo * 128 + lane * 4]);
            float d = wv.x * sv.x + wv.y * sv.y + wv.z * sv.z + wv.w * sv.w;
#pragma unroll
            for (int o = 16; o > 0; o >>= 1) d += __shfl_xor_sync(0xffffffffu, d, o);
            if (lane == 0) {
                d += bb[jo];
                if (i < 2) d = fmaxf(d, 0.f);
                nxt[jo] = d;
            }
        }
        __syncthreads();
        float* tmp = cur; cur = nxt; nxt = tmp;
    }
    float f = cur[j];
    float t2 = block_sumsq_128(f, red4);
    float sc2 = 1.f / fmaxf(sqrtf(t2), 1e-12f);
    g_repsneg[((size_t)c * NEG_ + n) * 128 + j] = f * sc2;
}

// ---------------------------------------------------------------------------
// dot + epilogue v5: MUFU-reduced (11 -> 8 transcendentals per px-class).
// 64-px x 16-class tile, FFMA dots (proven layout).
// ---------------------------------------------------------------------------
__global__ __launch_bounds__(256)
void dot_out_v5(float* __restrict__ out)
{
    extern __shared__ float smd[];
    float* e_s  = smd;                 // [128 ch][stride 68]
    float* rp_s = smd + 8704;          // [16 cls][128]
    float* rn_s = smd + 8704 + 2048;   // [16 cls][3][128]

    const int tid = threadIdx.x;
    const int b  = blockIdx.y;
    const int p0 = blockIdx.x * 64;
    const int c0 = blockIdx.z * 16;

    for (int i = tid; i < 8192; i += 256) {
        int px = i >> 7, ch = i & 127;
        e_s[ch * 68 + px] = g_emb[((size_t)(b * NPIX + p0 + px)) * 128 + ch];
    }
    for (int i = tid; i < 2048; i += 256) rp_s[i] = g_reps[c0 * EMB2_ + i];
    for (int i = tid; i < 6144; i += 256) rn_s[i] = g_repsneg[c0 * NEG_ * EMB2_ + i];
    __syncthreads();

    const int cc = tid >> 4;
    const int pg = tid & 15;
    const float* rpp = rp_s + cc * 128;
    const float* rn0 = rn_s + (cc * 3 + 0) * 128;
    const float* rn1 = rn_s + (cc * 3 + 1) * 128;
    const float* rn2 = rn_s + (cc * 3 + 2) * 128;

    float ap[4] = {0, 0, 0, 0};
    float a0[4] = {0, 0, 0, 0};
    float a1[4] = {0, 0, 0, 0};
    float a2[4] = {0, 0, 0, 0};

#pragma unroll 4
    for (int ch = 0; ch < 128; ++ch) {
        float4 ev = *reinterpret_cast<const float4*>(&e_s[ch * 68 + pg * 4]);
        float wp = rpp[ch], w0 = rn0[ch], w1 = rn1[ch], w2 = rn2[ch];
        ap[0] = fmaf(ev.x, wp, ap[0]); ap[1] = fmaf(ev.y, wp, ap[1]);
        ap[2] = fmaf(ev.z, wp, ap[2]); ap[3] = fmaf(ev.w, wp, ap[3]);
        a0[0] = fmaf(ev.x, w0, a0[0]); a0[1] = fmaf(ev.y, w0, a0[1]);
        a0[2] = fmaf(ev.z, w0, a0[2]); a0[3] = fmaf(ev.w, w0, a0[3]);
        a1[0] = fmaf(ev.x, w1, a1[0]); a1[1] = fmaf(ev.y, w1, a1[1]);
        a1[2] = fmaf(ev.z, w1, a1[2]); a1[3] = fmaf(ev.w, w1, a1[3]);
        a2[0] = fmaf(ev.x, w2, a2[0]); a2[1] = fmaf(ev.y, w2, a2[1]);
        a2[2] = fmaf(ev.z, w2, a2[2]); a2[3] = fmaf(ev.w, w2, a2[3]);
    }

    const int c = c0 + cc;
    const size_t S = (size_t)BATCH_ * NCLS_ * NPIX;
    float* out_cls  = out;
    float* out_csn  = out + S;
    float* out_dist = out + 2 * S;
    float* out_dneg = out + 3 * S;
    float* out_pori = out + 6 * S;

    const size_t base   = ((size_t)b * NCLS_ + c) * NPIX + p0 + pg * 4;
    const size_t dnbase = ((size_t)(b * NCLS_ + c) * 3) * NPIX + p0 + pg * 4;

#pragma unroll
    for (int jx = 0; jx < 4; ++jx) {
        // squared distances (no sqrt needed for the exp outputs)
        float d2p = fmaxf(2.f - 2.f * ap[jx], 0.f);
        float d20 = fmaxf(2.f - 2.f * a0[jx], 0.f);
        float d21 = fmaxf(2.f - 2.f * a1[jx], 0.f);
        float d22 = fmaxf(2.f - 2.f * a2[jx], 0.f);

        float dist = sqrtf(d2p);
        float dn0  = sqrtf(d20);
        float dn1  = sqrtf(d21);
        float dn2  = sqrtf(d22);

        // csn = max_i exp(-2 d2n_i) = exp(-2 min_i d2n_i)   (exp monotone)
        float mind2 = fminf(d20, fminf(d21, d22));
        float csn  = expf(-2.f * mind2);
        float pori = expf(-2.f * d2p);

        float minn = fminf(dn0, fminf(dn1, dn2));   // == sqrt(mind2), free
        float shifted = dist + 0.3f * fmaxf(2.f - minn, 0.f);
        float s2 = shifted * shifted;
        float pr = expf(-2.f * s2);
        // cls = ln(max(pr,eps)) - ln(max(1-pr,eps)); ln(pr) == -2 s2 when pr>=eps
        float ln_num = (pr >= 1e-5f) ? (-2.f * s2) : -11.5129254f;
        float ln_den = logf(fmaxf(1.f - pr, 1e-5f));
        float cls = ln_num - ln_den;

        out_cls [base + jx] = cls;
        out_csn [base + jx] = csn;
        out_dist[base + jx] = dist;
        out_pori[base + jx] = pori;
        out_dneg[dnbase + jx]            = dn0;
        out_dneg[dnbase + NPIX + jx]     = dn1;
        out_dneg[dnbase + 2 * NPIX + jx] = dn2;
    }
}

// ---------------------------------------------------------------------------
extern "C" void kernel_launch(void* const* d_in, const int* in_sizes, int n_in,
                              void* d_out, int out_size)
{
    const float* x      = (const float*)d_in[0];
    const float* w1     = (const float*)d_in[1];
    const float* b1     = (const float*)d_in[2];
    const float* gamma  = (const float*)d_in[3];
    const float* beta   = (const float*)d_in[4];
    const float* mean   = (const float*)d_in[5];
    const float* var    = (const float*)d_in[6];
    const float* w2     = (const float*)d_in[7];
    const float* b2     = (const float*)d_in[8];
    const float* rep_w  = (const float*)d_in[9];
    const float* rep_b  = (const float*)d_in[10];
    const float* neg_w  = (const float*)d_in[11];
    const float* neg_b  = (const float*)d_in[12];
    float* out = (float*)d_out;

    (void)in_sizes; (void)n_in; (void)out_size;

    const int CONV1_SMEM = (14112 + 9216) * 4;      // 93312 B  -> 2 CTAs/SM
    const int CONV2_SMEM = 192 * 132 * 4;           // 101376 B -> 2 CTAs/SM (Es overlay)
    cudaFuncSetAttribute(conv_tf32<1>, cudaFuncAttributeMaxDynamicSharedMemorySize, CONV1_SMEM);
    cudaFuncSetAttribute(conv_tf32<2>, cudaFuncAttributeMaxDynamicSharedMemorySize, CONV2_SMEM);
    cudaFuncSetAttribute(dot_out_v5,   cudaFuncAttributeMaxDynamicSharedMemorySize, 67584);

    float *wf1p, *wf2p;
    cudaGetSymbolAddress((void**)&wf1p, g_wf1);
    cudaGetSymbolAddress((void**)&wf2p, g_wf2);

    // pre-passes
    transpose_x_kernel<<<dim3(NPIX / 32, BATCH_), 256>>>(x);
    wprep_kernel<<<(EMB1_ * 2304 + 255) / 256, 256>>>(w1, wf1p, EMB1_ * 2304);
    wprep_kernel<<<(EMB2_ * 2304 + 255) / 256, 256>>>(w2, wf2p, EMB2_ * 2304);

    // conv1 + BN (tf32 mma, R14-proven mt=2/nt=12)  [profiled slot]
    conv_tf32<1><<<dim3(48, BATCH_, 2), 256, CONV1_SMEM>>>(b1, gamma, beta, mean, var);

    // reps (independent)
    prep_reps_v6<<<dim3(NCLS_, NEG_), 128>>>(rep_w, rep_b, neg_w, neg_b);

    // conv2 + fused bias + L2 normalize
    conv_tf32<2><<<dim3(48, BATCH_, 1), 256, CONV2_SMEM>>>(b2, nullptr, nullptr, nullptr, nullptr);

    // fused dot + outputs (MUFU-reduced epilogue)
    dot_out_v5<<<dim3(NPIX / 64, BATCH_, NCLS_ / 16), 256, 67584>>>(out);
}

// round 17
// speedup vs baseline: 1.1507x; 1.1108x over previous
#include <cuda_runtime.h>
#include <cstdint>

#define NPIX   9216
#define HW_    96
#define CIN_   256
#define EMB1_  256
#define EMB2_  128
#define NCLS_  80
#define NEG_   3
#define BATCH_ 8

// ---------------- device scratch (allocation-free) ----------------
__device__ float g_xf [(size_t)BATCH_ * NPIX * CIN_];   // x NHWC, tf32-rounded fp32
__device__ float g_hf [(size_t)BATCH_ * NPIX * EMB1_];  // conv1+BN out, tf32-rounded fp32
__device__ float g_emb[(size_t)BATCH_ * NPIX * EMB2_];  // conv2 out, NORMALIZED, pixel-major
__device__ float g_wf1[EMB1_ * 9 * 256];                // W1 as [co][tap][ci], tf32-rounded
__device__ float g_wf2[EMB2_ * 9 * 256];                // W2 same
__device__ float g_reps[NCLS_ * EMB2_];
__device__ float g_repsneg[NCLS_ * NEG_ * EMB2_];

// ---------------- helpers ----------------
__device__ __forceinline__ float to_tf32(float x) {
    uint32_t u;
    asm("cvt.rna.tf32.f32 %0, %1;" : "=r"(u) : "f"(x));
    return __uint_as_float(u);
}
__device__ __forceinline__ uint32_t smem_u32(const void* p) {
    uint32_t a;
    asm("{ .reg .u64 t; cvta.to.shared.u64 t, %1; cvt.u32.u64 %0, t; }" : "=r"(a) : "l"(p));
    return a;
}
#define MMA_TF32(d, a, b0, b1) \
    asm volatile("mma.sync.aligned.m16n8k8.row.col.f32.tf32.tf32.f32 " \
        "{%0,%1,%2,%3}, {%4,%5,%6,%7}, {%8,%9}, {%0,%1,%2,%3};" \
        : "+f"((d)[0]), "+f"((d)[1]), "+f"((d)[2]), "+f"((d)[3]) \
        : "r"((a)[0]), "r"((a)[1]), "r"((a)[2]), "r"((a)[3]), "r"(b0), "r"(b1))
#define CP_ASYNC16(dst, src, sz) \
    asm volatile("cp.async.cg.shared.global [%0], [%1], 16, %2;" \
        :: "r"(dst), "l"(src), "r"(sz) : "memory")
#define CP_COMMIT() asm volatile("cp.async.commit_group;" ::: "memory")
#define CP_WAIT0()  asm volatile("cp.async.wait_group 0;" ::: "memory")

// ---------------------------------------------------------------------------
// pre-pass: x NCHW fp32 -> NHWC tf32-rounded fp32
// ---------------------------------------------------------------------------
__global__ __launch_bounds__(256)
void transpose_x_kernel(const float* __restrict__ x)
{
    __shared__ float s32[256 * 33];
    const int tid = threadIdx.x;
    const int b = blockIdx.y;
    const int p0 = blockIdx.x * 32;
    const int pxr = tid & 31, chb = tid >> 5;
#pragma unroll 4
    for (int pass = 0; pass < 32; ++pass) {
        int ch = pass * 8 + chb;
        s32[ch * 33 + pxr] = to_tf32(x[((size_t)(b * 256 + ch)) * NPIX + p0 + pxr]);
    }
    __syncthreads();
    for (int px = 0; px < 32; ++px) {
        g_xf[((size_t)(b * NPIX + p0 + px)) * 256 + tid] = s32[tid * 33 + px];
    }
}

// ---------------------------------------------------------------------------
// pre-pass: W [co][256][3][3] fp32 -> [co][tap][ci] tf32-rounded fp32
// ---------------------------------------------------------------------------
__global__ __launch_bounds__(256)
void wprep_kernel(const float* __restrict__ w, float* __restrict__ dst, int total)
{
    int i = blockIdx.x * 256 + threadIdx.x;
    if (i >= total) return;
    int co = i / 2304, r = i - co * 2304;
    int t = r >> 8;
    int ci = r & 255;
    dst[i] = to_tf32(w[((size_t)(co * 256 + ci)) * 9 + t]);
}

// ---------------------------------------------------------------------------
// staging via cp.async (16B, zero-fill OOB); smem row stride 36 floats
// ---------------------------------------------------------------------------
__device__ __forceinline__ void stage_X_async(uint32_t xdst, const float* __restrict__ src,
                                              int b, int y0, int c, int tid)
{
    for (int i = tid; i < 3136; i += 256) {     // 4 rows x 98 xpos x 8 groups
        int pos = i >> 3, g = i & 7;
        int yrow = pos / 98, xpos = pos - yrow * 98;
        int y = y0 + yrow - 1, xc = xpos - 1;
        int ok = ((unsigned)y < 96u) && ((unsigned)xc < 96u);
        const float* gs = ok ? (src + ((size_t)(b * NPIX + y * 96 + xc)) * 256 + c * 32 + g * 4)
                             : src;
        CP_ASYNC16(xdst + (uint32_t)(pos * 144 + g * 16), gs, ok ? 16 : 0);
    }
}
__device__ __forceinline__ void stage_W_async(uint32_t wdst, const float* __restrict__ wsrc,
                                              int co0, int c, int tap, int tid)
{
    for (int i = tid; i < 1024; i += 256) {     // 128 co x 8 groups
        int co = i >> 3, g = i & 7;
        const float* gs = wsrc + ((size_t)((co0 + co) * 9 + tap)) * 256 + c * 32 + g * 4;
        CP_ASYNC16(wdst + (uint32_t)(co * 144 + g * 16), gs, 16);
    }
}

// ---------------------------------------------------------------------------
// tf32 mma conv (R14-proven, 481us conv1): 2 CTAs/SM, cp.async pipeline,
// scalar LDS.32 fragments, mt=2/nt=12 warp tiles.
// STAGE 1: g_xf -> g_hf (BN folded).
// STAGE 2: g_hf -> g_emb (bias + FUSED L2 normalize).
// ---------------------------------------------------------------------------
template<int STAGE>
__global__ __launch_bounds__(256, 2)
void conv_tf32(const float* __restrict__ bias,
               const float* __restrict__ gamma,
               const float* __restrict__ beta,
               const float* __restrict__ mean,
               const float* __restrict__ var)
{
    extern __shared__ float smf[];
    float* Xall = smf;               // [14112]  (4 rows x 98 x stride36)
    float* Wall = smf + 14112;       // [2][4608] (128 co x stride36)

    const int tid = threadIdx.x, wid = tid >> 5, lane = tid & 31;
    const int y0 = blockIdx.x * 2;
    const int b  = blockIdx.y;
    const int co0 = blockIdx.z * 128;
    const int wq = wid & 3, wh = wid >> 2;
    const int gid = lane >> 2, tig = lane & 3;

    const float* __restrict__ src  = (STAGE == 1) ? g_xf : g_hf;
    const float* __restrict__ wsrc = (STAGE == 1) ? g_wf1 : g_wf2;

    const uint32_t smb = smem_u32(smf);
    const uint32_t xbase = smb;
    const uint32_t wbase[2] = { smb + 14112u * 4u, smb + (14112u + 4608u) * 4u };

    float acc[2][12][4];
#pragma unroll
    for (int m = 0; m < 2; ++m)
#pragma unroll
        for (int n = 0; n < 12; ++n)
#pragma unroll
            for (int q = 0; q < 4; ++q) acc[m][n][q] = 0.f;

    int aidx[2], xidx[12];
#pragma unroll
    for (int mi = 0; mi < 2; ++mi)
        aidx[mi] = (wq * 32 + mi * 16 + gid) * 36 + tig;
#pragma unroll
    for (int p = 0; p < 12; ++p)
        xidx[p] = (wh * 98 + p * 8 + gid) * 36 + tig;

    // prologue
    stage_X_async(xbase, src, b, y0, 0, tid);
    stage_W_async(wbase[0], wsrc, co0, 0, 0, tid);
    CP_COMMIT();

    int it = 0;
    for (int c = 0; c < 8; ++c) {
        for (int tap = 0; tap < 9; ++tap, ++it) {
            CP_WAIT0();
            __syncthreads();
            if (it < 71) {
                const int itn = it + 1, cn = itn / 9, tapn = itn - cn * 9;
                stage_W_async(wbase[itn & 1], wsrc, co0, cn, tapn, tid);
                CP_COMMIT();
            }
            const uint32_t* Wsu = reinterpret_cast<const uint32_t*>(Wall + (it & 1) * 4608);
            const uint32_t* Xhu = reinterpret_cast<const uint32_t*>(Xall);
            const int kr = tap / 3, kc = tap - kr * 3;
            const int toff = (kr * 98 + kc) * 36;
#pragma unroll
            for (int ks = 0; ks < 4; ++ks) {
                const int k0 = ks * 8;
                uint32_t a[2][4];
#pragma unroll
                for (int mi = 0; mi < 2; ++mi) {
                    a[mi][0] = Wsu[aidx[mi] + k0];
                    a[mi][1] = Wsu[aidx[mi] + k0 + 8 * 36];
                    a[mi][2] = Wsu[aidx[mi] + k0 + 4];
                    a[mi][3] = Wsu[aidx[mi] + k0 + 8 * 36 + 4];
                }
#pragma unroll
                for (int p = 0; p < 12; ++p) {
                    uint32_t b0 = Xhu[xidx[p] + toff + k0];
                    uint32_t b1 = Xhu[xidx[p] + toff + k0 + 4];
                    MMA_TF32(acc[0][p], a[0], b0, b1);
                    MMA_TF32(acc[1][p], a[1], b0, b1);
                }
            }
        }
        if (c < 7) {
            __syncthreads();                       // all X reads of this chunk done
            stage_X_async(xbase, src, b, y0, c + 1, tid);
            CP_COMMIT();
        }
    }

    if (STAGE == 1) {
        const size_t pixb = (size_t)b * NPIX + (size_t)(y0 + wh) * 96;
#pragma unroll
        for (int mi = 0; mi < 2; ++mi) {
            const int clo = co0 + wq * 32 + mi * 16 + gid;
            const int chi = clo + 8;
            float blo = bias[clo], bhi = bias[chi];
            float slo = gamma[clo] * rsqrtf(var[clo] + 1e-5f);
            float shi = gamma[chi] * rsqrtf(var[chi] + 1e-5f);
            float mlo = mean[clo], mhi = mean[chi];
            float elo = beta[clo], ehi = beta[chi];
#pragma unroll
            for (int n = 0; n < 12; ++n) {
                const int px0 = n * 8 + tig * 2;
#pragma unroll
                for (int j = 0; j < 2; ++j) {
                    float vlo = (acc[mi][n][j]     + blo - mlo) * slo + elo;
                    float vhi = (acc[mi][n][j + 2] + bhi - mhi) * shi + ehi;
                    const size_t pix = pixb + px0 + j;
                    g_hf[pix * 256 + clo] = to_tf32(vlo);
                    g_hf[pix * 256 + chi] = to_tf32(vhi);
                }
            }
        }
    } else {
        // fused bias + L2 normalize via smem overlay Es[192][132]
        __syncthreads();
        float* Es = smf;
#pragma unroll
        for (int mi = 0; mi < 2; ++mi) {
            const int clo = wq * 32 + mi * 16 + gid;     // co0 == 0 for conv2
            const int chi = clo + 8;
            float blo = bias[clo], bhi = bias[chi];
#pragma unroll
            for (int n = 0; n < 12; ++n) {
                const int lp = wh * 96 + n * 8 + tig * 2;
#pragma unroll
                for (int j = 0; j < 2; ++j) {
                    Es[(lp + j) * 132 + clo] = acc[mi][n][j]     + blo;
                    Es[(lp + j) * 132 + chi] = acc[mi][n][j + 2] + bhi;
                }
            }
        }
        __syncthreads();
        const size_t pixb = (size_t)b * NPIX + (size_t)y0 * 96;
        for (int p = wid * 24; p < wid * 24 + 24; ++p) {
            float4 v = *reinterpret_cast<const float4*>(&Es[p * 132 + lane * 4]);
            float ss = v.x * v.x + v.y * v.y + v.z * v.z + v.w * v.w;
#pragma unroll
            for (int o = 16; o > 0; o >>= 1) ss += __shfl_xor_sync(0xffffffffu, ss, o);
            float sc = 1.f / fmaxf(sqrtf(ss), 1e-12f);
            v.x *= sc; v.y *= sc; v.z *= sc; v.w *= sc;
            *reinterpret_cast<float4*>(&g_emb[(pixb + p) * 128 + lane * 4]) = v;
        }
    }
}

// ---------------------------------------------------------------------------
// reps prep v6: grid (class, neg) -> serial depth 3 layers.
// ---------------------------------------------------------------------------
__device__ __forceinline__ float block_sumsq_128(float v, float* red4)
{
    float s = v * v;
#pragma unroll
    for (int o = 16; o > 0; o >>= 1) s += __shfl_xor_sync(0xffffffffu, s, o);
    const int wid = threadIdx.x >> 5, lane = threadIdx.x & 31;
    if (lane == 0) red4[wid] = s;
    __syncthreads();
    float tot = red4[0] + red4[1] + red4[2] + red4[3];
    __syncthreads();
    return tot;
}

__global__ __launch_bounds__(128)
void prep_reps_v6(const float* __restrict__ rep_w,
                  const float* __restrict__ rep_b,
                  const float* __restrict__ neg_w,
                  const float* __restrict__ neg_b)
{
    __shared__ float h_a[128];
    __shared__ float h_b[128];
    __shared__ float red4[4];

    const int j = threadIdx.x, c = blockIdx.x, n = blockIdx.y;
    const int w = j >> 5, lane = j & 31;

    float v = rep_w[c * 128 + j] + rep_b[c * 128 + j];
    float tot = block_sumsq_128(v, red4);
    float scale = 1.f / fmaxf(sqrtf(tot), 1e-12f);
    h_a[j] = v * scale;
    if (n == 0) g_reps[c * 128 + j] = v * scale;
    __syncthreads();

    float* cur = h_a;
    float* nxt = h_b;
#pragma unroll
    for (int i = 0; i < 3; ++i) {
        const float* W = neg_w + (size_t)((n * 3 + i) * 128) * 128;
        const float* bb = neg_b + (n * 3 + i) * 128;
        float4 sv = *reinterpret_cast<const float4*>(&cur[lane * 4]);
#pragma unroll 4
        for (int t = 0; t < 32; ++t) {
            int jo = w * 32 + t;
            float4 wv = *reinterpret_cast<const float4*>(&W[(size_t)jo * 128 + lane * 4]);
            float d = wv.x * sv.x + wv.y * sv.y + wv.z * sv.z + wv.w * sv.w;
#pragma unroll
            for (int o = 16; o > 0; o >>= 1) d += __shfl_xor_sync(0xffffffffu, d, o);
            if (lane == 0) {
                d += bb[jo];
                if (i < 2) d = fmaxf(d, 0.f);
                nxt[jo] = d;
            }
        }
        __syncthreads();
        float* tmp = cur; cur = nxt; nxt = tmp;
    }
    float f = cur[j];
    float t2 = block_sumsq_128(f, red4);
    float sc2 = 1.f / fmaxf(sqrtf(t2), 1e-12f);
    g_repsneg[((size_t)c * NEG_ + n) * 128 + j] = f * sc2;
}

// ---------------------------------------------------------------------------
// dot via tf32 mma v2: block = 64 px x 64 reps (16 classes), 256 threads,
// 3 CTAs/SM. 8 warps = 4 rep-groups(16) x 2 px-groups(32). Warp: mt=1, nt=4.
// Accumulators -> smem overlay dots[64 px][stride 68] (bank-perfect writes),
// then v5 MUFU-reduced epilogue with coalesced stores.
// rep r (0..63): class = c0 + (r>>2), kind = r&3 (0=pos, 1..3=neg).
// ---------------------------------------------------------------------------
__global__ __launch_bounds__(256)
void dot_mma2(float* __restrict__ out)
{
    extern __shared__ float sd[];
    float* reps_s = sd;            // [64 r][132]
    float* emb_s  = sd + 8448;     // [64 px][132]
    float* dots_s = sd;            // overlay [64 px][68]

    const int tid = threadIdx.x, wid = tid >> 5, lane = tid & 31;
    const int g = lane >> 2, tig = lane & 3;
    const int b  = blockIdx.y;
    const int p0 = blockIdx.x * 64;
    const int c0 = blockIdx.z * 16;

    for (int i = tid; i < 8192; i += 256) {
        int r = i >> 7, k = i & 127;
        int cls = c0 + (r >> 2), kind = r & 3;
        float v = (kind == 0) ? g_reps[cls * 128 + k]
                              : g_repsneg[(cls * 3 + (kind - 1)) * 128 + k];
        reps_s[r * 132 + k] = v;
    }
    for (int i = tid; i < 8192; i += 256) {
        int px = i >> 7, ch = i & 127;
        emb_s[px * 132 + ch] = g_emb[((size_t)(b * NPIX + p0 + px)) * 128 + ch];
    }
    __syncthreads();

    const int wr = wid >> 1;   // rep group (16 reps)
    const int wp = wid & 1;    // px group (32 px)
    float acc[4][4];
#pragma unroll
    for (int ni = 0; ni < 4; ++ni)
#pragma unroll
        for (int q = 0; q < 4; ++q) acc[ni][q] = 0.f;

    const uint32_t* ru = reinterpret_cast<const uint32_t*>(reps_s);
    const uint32_t* eu = reinterpret_cast<const uint32_t*>(emb_s);
    const int abase = (wr * 16 + g) * 132 + tig;
    int bidx[4];
#pragma unroll
    for (int ni = 0; ni < 4; ++ni)
        bidx[ni] = (wp * 32 + ni * 8 + g) * 132 + tig;

#pragma unroll 4
    for (int ks = 0; ks < 16; ++ks) {
        const int k0 = ks * 8;
        uint32_t a[4];
        a[0] = ru[abase + k0];
        a[1] = ru[abase + k0 + 8 * 132];
        a[2] = ru[abase + k0 + 4];
        a[3] = ru[abase + k0 + 8 * 132 + 4];
#pragma unroll
        for (int ni = 0; ni < 4; ++ni) {
            uint32_t b0 = eu[bidx[ni] + k0];
            uint32_t b1 = eu[bidx[ni] + k0 + 4];
            MMA_TF32(acc[ni], a, b0, b1);
        }
    }
    __syncthreads();   // all operand reads done before overlay writes

    // overlay: dots_s[px*68 + rep]  (banks 8*tig+g -> conflict-free writes)
    const int rep_lo = wr * 16 + g;
#pragma unroll
    for (int ni = 0; ni < 4; ++ni) {
        int px = wp * 32 + ni * 8 + tig * 2;
        dots_s[px * 68 + rep_lo]           = acc[ni][0];
        dots_s[(px + 1) * 68 + rep_lo]     = acc[ni][1];
        dots_s[px * 68 + rep_lo + 8]       = acc[ni][2];
        dots_s[(px + 1) * 68 + rep_lo + 8] = acc[ni][3];
    }
    __syncthreads();

    // epilogue: 1024 (px,cls) items, 4 per thread, px-fastest (coalesced STG)
    const size_t S = (size_t)BATCH_ * NCLS_ * NPIX;
    float* out_cls  = out;
    float* out_csn  = out + S;
    float* out_dist = out + 2 * S;
    float* out_dneg = out + 3 * S;
    float* out_pori = out + 6 * S;

#pragma unroll
    for (int itx = 0; itx < 4; ++itx) {
        const int idx = itx * 256 + tid;
        const int px  = idx & 63;
        const int cl  = idx >> 6;          // 0..15
        const float* q = &dots_s[px * 68 + cl * 4];
        float d2p = fmaxf(2.f - 2.f * q[0], 0.f);
        float d20 = fmaxf(2.f - 2.f * q[1], 0.f);
        float d21 = fmaxf(2.f - 2.f * q[2], 0.f);
        float d22 = fmaxf(2.f - 2.f * q[3], 0.f);

        float dist = sqrtf(d2p);
        float dn0  = sqrtf(d20);
        float dn1  = sqrtf(d21);
        float dn2  = sqrtf(d22);

        float mind2 = fminf(d20, fminf(d21, d22));
        float csn  = expf(-2.f * mind2);
        float pori = expf(-2.f * d2p);

        float minn = fminf(dn0, fminf(dn1, dn2));
        float shifted = dist + 0.3f * fmaxf(2.f - minn, 0.f);
        float s2 = shifted * shifted;
        float pr = expf(-2.f * s2);
        float ln_num = (pr >= 1e-5f) ? (-2.f * s2) : -11.5129254f;
        float ln_den = logf(fmaxf(1.f - pr, 1e-5f));
        float cls = ln_num - ln_den;

        const int c = c0 + cl;
        const size_t base   = ((size_t)b * NCLS_ + c) * NPIX + p0 + px;
        const size_t dnbase = ((size_t)(b * NCLS_ + c) * 3) * NPIX + p0 + px;

        out_cls [base] = cls;
        out_csn [base] = csn;
        out_dist[base] = dist;
        out_pori[base] = pori;
        out_dneg[dnbase]            = dn0;
        out_dneg[dnbase + NPIX]     = dn1;
        out_dneg[dnbase + 2 * NPIX] = dn2;
    }
}

// ---------------------------------------------------------------------------
extern "C" void kernel_launch(void* const* d_in, const int* in_sizes, int n_in,
                              void* d_out, int out_size)
{
    const float* x      = (const float*)d_in[0];
    const float* w1     = (const float*)d_in[1];
    const float* b1     = (const float*)d_in[2];
    const float* gamma  = (const float*)d_in[3];
    const float* beta   = (const float*)d_in[4];
    const float* mean   = (const float*)d_in[5];
    const float* var    = (const float*)d_in[6];
    const float* w2     = (const float*)d_in[7];
    const float* b2     = (const float*)d_in[8];
    const float* rep_w  = (const float*)d_in[9];
    const float* rep_b  = (const float*)d_in[10];
    const float* neg_w  = (const float*)d_in[11];
    const float* neg_b  = (const float*)d_in[12];
    float* out = (float*)d_out;

    (void)in_sizes; (void)n_in; (void)out_size;

    const int CONV1_SMEM = (14112 + 9216) * 4;      // 93312 B  -> 2 CTAs/SM
    const int CONV2_SMEM = 192 * 132 * 4;           // 101376 B -> 2 CTAs/SM (Es overlay)
    const int DOT_SMEM   = (8448 + 8448) * 4;       // 67584 B  -> 3 CTAs/SM
    cudaFuncSetAttribute(conv_tf32<1>, cudaFuncAttributeMaxDynamicSharedMemorySize, CONV1_SMEM);
    cudaFuncSetAttribute(conv_tf32<2>, cudaFuncAttributeMaxDynamicSharedMemorySize, CONV2_SMEM);
    cudaFuncSetAttribute(dot_mma2,     cudaFuncAttributeMaxDynamicSharedMemorySize, DOT_SMEM);

    float *wf1p, *wf2p;
    cudaGetSymbolAddress((void**)&wf1p, g_wf1);
    cudaGetSymbolAddress((void**)&wf2p, g_wf2);

    // pre-passes
    transpose_x_kernel<<<dim3(NPIX / 32, BATCH_), 256>>>(x);
    wprep_kernel<<<(EMB1_ * 2304 + 255) / 256, 256>>>(w1, wf1p, EMB1_ * 2304);
    wprep_kernel<<<(EMB2_ * 2304 + 255) / 256, 256>>>(w2, wf2p, EMB2_ * 2304);

    // conv1 + BN (tf32 mma, R14-proven)  [profiled slot]
    conv_tf32<1><<<dim3(48, BATCH_, 2), 256, CONV1_SMEM>>>(b1, gamma, beta, mean, var);

    // reps (independent)
    prep_reps_v6<<<dim3(NCLS_, NEG_), 128>>>(rep_w, rep_b, neg_w, neg_b);

    // conv2 + fused bias + L2 normalize
    conv_tf32<2><<<dim3(48, BATCH_, 1), 256, CONV2_SMEM>>>(b2, nullptr, nullptr, nullptr, nullptr);

    // dot via tf32 mma + fused epilogue
    dot_mma2<<<dim3(NPIX / 64, BATCH_, NCLS_ / 16), 256, DOT_SMEM>>>(out);
}